// round 5
// baseline (speedup 1.0000x reference)
#include <cuda_runtime.h>
#include <math.h>

#define N_NODES 10000
#define N_EDGES 160000
#define ETOT (N_EDGES + N_NODES)   /* 170000 with self loops */
#define F_IN 768
#define H1 4
#define CDIM 128
#define HC1 (H1 * CDIM)            /* 512 */
#define NG 16
#define NOUT 10

// ---------------- scratch (device globals; no runtime allocation) -------------
#define Z_DEG  0
#define Z_POOL (Z_DEG + N_NODES)
#define Z_CNT  (Z_POOL + NG * CDIM)
#define ZTOT   (Z_CNT + NG)
__device__ float g_zero[ZTOT];

__device__ int   g_row_ptr[N_NODES + 1];
__device__ int   g_cursor [N_NODES];
__device__ int   g_csr_src[ETOT];

__device__ float g_h1  [N_NODES * HC1];
__device__ float g_out1[N_NODES * HC1];
__device__ float g_als1[N_NODES * H1];
__device__ float g_ald1[N_NODES * H1];

__device__ float g_h2  [N_NODES * CDIM];
__device__ float g_als2[N_NODES];
__device__ float g_ald2[N_NODES];

// ---------------- utility ------------------------------------------------------
__global__ void fill4_kernel(float4* p, float v, int n4) {
    int i = blockIdx.x * blockDim.x + threadIdx.x;
    if (i < n4) p[i] = make_float4(v, v, v, v);
}

// ---------------- CSR build + pool counts --------------------------------------
__global__ void hist_kernel(const int* __restrict__ ei, int* __restrict__ deg,
                            const int* __restrict__ batch, float* __restrict__ cnt) {
    int idx = blockIdx.x * blockDim.x + threadIdx.x;
    if (idx < N_NODES) atomicAdd(&cnt[batch[idx]], 1.0f);
    if (idx >= ETOT) return;
    int d = (idx < N_EDGES) ? ei[N_EDGES + idx] : idx - N_EDGES;
    atomicAdd(&deg[d], 1);
}

__global__ __launch_bounds__(1024)
void scan_kernel(const int* __restrict__ deg, int* __restrict__ row_ptr,
                 int* __restrict__ cursor) {
    __shared__ int sm[1024];
    const int t = threadIdx.x;
    const int base = t * 10;
    int loc[10];
    int s = 0;
#pragma unroll
    for (int i = 0; i < 10; i++) {
        int idx = base + i;
        int v = (idx < N_NODES) ? deg[idx] : 0;
        loc[i] = s;
        s += v;
    }
    sm[t] = s;
    __syncthreads();
    for (int off = 1; off < 1024; off <<= 1) {
        int v = 0;
        if (t >= off) v = sm[t - off];
        __syncthreads();
        if (t >= off) sm[t] += v;
        __syncthreads();
    }
    int pre = (t > 0) ? sm[t - 1] : 0;
#pragma unroll
    for (int i = 0; i < 10; i++) {
        int idx = base + i;
        if (idx < N_NODES) {
            row_ptr[idx] = pre + loc[i];
            cursor[idx]  = pre + loc[i];
        }
    }
    if (t == 0) row_ptr[N_NODES] = ETOT;
}

__global__ void scatter_kernel(const int* __restrict__ ei, int* __restrict__ cursor,
                               int* __restrict__ csr_src) {
    int idx = blockIdx.x * blockDim.x + threadIdx.x;
    if (idx >= ETOT) return;
    int s, d;
    if (idx < N_EDGES) { s = ei[idx]; d = ei[N_EDGES + idx]; }
    else               { s = d = idx - N_EDGES; }
    int pos = atomicAdd(&cursor[d], 1);
    csr_src[pos] = s;
}

// ---------------- TF32 tensor-core GEMM, 4-stage cp.async pipeline ------------
#define BK 16
#define A_PAD 20
#define B_PAD 136
#define STAGES 4
#define A_STG (128 * A_PAD)
#define B_STG (BK * B_PAD)
#define GEMM_SMEM (STAGES * (A_STG + B_STG) * 4)

__device__ __forceinline__ unsigned cvta_s(const void* p) {
    return (unsigned)__cvta_generic_to_shared(p);
}
__device__ __forceinline__ void cp_async16(unsigned s, const void* g) {
    asm volatile("cp.async.ca.shared.global [%0], [%1], 16;\n" :: "r"(s), "l"(g));
}
__device__ __forceinline__ void cp_commit() { asm volatile("cp.async.commit_group;\n"); }
__device__ __forceinline__ void cp_wait2() { asm volatile("cp.async.wait_group 2;\n"); }
__device__ __forceinline__ void cp_wait1() { asm volatile("cp.async.wait_group 1;\n"); }
__device__ __forceinline__ void cp_wait0() { asm volatile("cp.async.wait_group 0;\n"); }
__device__ __forceinline__ unsigned f2tf32(float f) {
    unsigned u;
    asm("cvt.rna.tf32.f32 %0, %1;\n" : "=r"(u) : "f"(f));
    return u;
}

__global__ __launch_bounds__(256)
void gemm_tf32(const float* __restrict__ A, const float* __restrict__ B,
               float* __restrict__ Cm, int M, int N, int K) {
    extern __shared__ float smem_dyn[];
    float* As = smem_dyn;                    // [STAGES][A_STG]
    float* Bs = smem_dyn + STAGES * A_STG;   // [STAGES][B_STG]

    const int tid  = threadIdx.x;
    const int lane = tid & 31;
    const int warp = tid >> 5;
    const int wm = warp & 1;
    const int wn = warp >> 1;
    const int m_base = wm * 64;
    const int n_base = wn * 32;
    const int g = lane >> 2;
    const int t = lane & 3;
    const int row0 = blockIdx.y * 128;
    const int col0 = blockIdx.x * 128;

    float acc[4][4][4];
#pragma unroll
    for (int i = 0; i < 4; i++)
#pragma unroll
        for (int j = 0; j < 4; j++)
#pragma unroll
            for (int r = 0; r < 4; r++) acc[i][j][r] = 0.f;

    const int a_row0c = tid >> 2, a_c = (tid & 3);
    const int b_k0c   = tid >> 5, b_n = (tid & 31);
    const int KT = K / BK;

    auto load_tile = [&](int kt, int buf) {
        const int k0 = kt * BK;
        float* Ab = As + buf * A_STG;
        float* Bb = Bs + buf * B_STG;
#pragma unroll
        for (int h = 0; h < 2; h++) {
            int row = a_row0c + h * 64;
            int grow = row0 + row;
            if (grow >= M) grow = M - 1;
            cp_async16(cvta_s(&Ab[row * A_PAD + a_c * 4]),
                       &A[(size_t)grow * K + k0 + a_c * 4]);
        }
#pragma unroll
        for (int h = 0; h < 2; h++) {
            int k = b_k0c + h * 8;
            cp_async16(cvta_s(&Bb[k * B_PAD + b_n * 4]),
                       &B[(size_t)(k0 + k) * N + col0 + b_n * 4]);
        }
        cp_commit();
    };

    // prologue: fill 3 stages
    for (int s = 0; s < STAGES - 1 && s < KT; s++) load_tile(s, s);

    for (int kt = 0; kt < KT; kt++) {
        const int buf = kt & (STAGES - 1);
        const int remaining = KT - 1 - kt;
        if (remaining >= 2) cp_wait2();
        else if (remaining == 1) cp_wait1();
        else cp_wait0();
        __syncthreads();
        if (kt + STAGES - 1 < KT) load_tile(kt + STAGES - 1, (kt + STAGES - 1) & (STAGES - 1));

        const float* Ab = As + buf * A_STG;
        const float* Bb = Bs + buf * B_STG;
#pragma unroll
        for (int kk = 0; kk < 2; kk++) {
            const int ks = kk * 8;
            unsigned a[4][4];
#pragma unroll
            for (int mf = 0; mf < 4; mf++) {
                const int r = m_base + mf * 16;
                a[mf][0] = f2tf32(Ab[(r + g)     * A_PAD + ks + t]);
                a[mf][1] = f2tf32(Ab[(r + g + 8) * A_PAD + ks + t]);
                a[mf][2] = f2tf32(Ab[(r + g)     * A_PAD + ks + t + 4]);
                a[mf][3] = f2tf32(Ab[(r + g + 8) * A_PAD + ks + t + 4]);
            }
            unsigned b[4][2];
#pragma unroll
            for (int nf = 0; nf < 4; nf++) {
                const int c = n_base + nf * 8 + g;
                b[nf][0] = f2tf32(Bb[(ks + t)     * B_PAD + c]);
                b[nf][1] = f2tf32(Bb[(ks + t + 4) * B_PAD + c]);
            }
#pragma unroll
            for (int mf = 0; mf < 4; mf++)
#pragma unroll
                for (int nf = 0; nf < 4; nf++) {
                    asm volatile(
                        "mma.sync.aligned.m16n8k8.row.col.f32.tf32.tf32.f32 "
                        "{%0,%1,%2,%3}, {%4,%5,%6,%7}, {%8,%9}, {%0,%1,%2,%3};\n"
                        : "+f"(acc[mf][nf][0]), "+f"(acc[mf][nf][1]),
                          "+f"(acc[mf][nf][2]), "+f"(acc[mf][nf][3])
                        : "r"(a[mf][0]), "r"(a[mf][1]), "r"(a[mf][2]), "r"(a[mf][3]),
                          "r"(b[nf][0]), "r"(b[nf][1]));
                }
        }
        __syncthreads();
    }

#pragma unroll
    for (int mf = 0; mf < 4; mf++) {
        const int r0 = row0 + m_base + mf * 16 + g;
        const int r1 = r0 + 8;
#pragma unroll
        for (int nf = 0; nf < 4; nf++) {
            const int c = col0 + n_base + nf * 8 + t * 2;
            if (r0 < M)
                *(float2*)&Cm[(size_t)r0 * N + c] = make_float2(acc[mf][nf][0], acc[mf][nf][1]);
            if (r1 < M)
                *(float2*)&Cm[(size_t)r1 * N + c] = make_float2(acc[mf][nf][2], acc[mf][nf][3]);
        }
    }
}

// ---------------- attention logits: warp per (node, head), multi-node blocks ---
template<int H>
__global__ __launch_bounds__(256)
void att_logits(const float* __restrict__ feat,
                const float* __restrict__ asrc,
                const float* __restrict__ adst,
                float* __restrict__ osrc, float* __restrict__ odst) {
    const int wpb  = 256 / 32;                 // 8 warps
    const int gw   = blockIdx.x * wpb + (threadIdx.x >> 5);
    const int lane = threadIdx.x & 31;
    const int n = gw / H, h = gw - n * H;
    if (n >= N_NODES) return;
    const float* f = feat + ((size_t)n * H + h) * CDIM;
    float ss = 0.f, sd = 0.f;
#pragma unroll
    for (int c = lane; c < CDIM; c += 32) {
        float v = f[c];
        ss = fmaf(v, asrc[h * CDIM + c], ss);
        sd = fmaf(v, adst[h * CDIM + c], sd);
    }
#pragma unroll
    for (int o = 16; o; o >>= 1) {
        ss += __shfl_down_sync(0xffffffffu, ss, o);
        sd += __shfl_down_sync(0xffffffffu, sd, o);
    }
    if (lane == 0) { osrc[n * H + h] = ss; odst[n * H + h] = sd; }
}

// ---------------- fused softmax + aggregate (+bias/relu, opt pool) -----------
template<int H, bool POOL>
__global__ __launch_bounds__(256)
void gat_fused(const int* __restrict__ row_ptr,
               const int* __restrict__ csr_src,
               const float* __restrict__ feat,
               const float* __restrict__ als,
               const float* __restrict__ ald,
               const float* __restrict__ bias,
               float* __restrict__ out,
               const int* __restrict__ batch,
               float* __restrict__ pool) {
    const int gw   = (blockIdx.x * blockDim.x + threadIdx.x) >> 5;
    const int lane = threadIdx.x & 31;
    const int n = gw / H, h = gw - n * H;
    if (n >= N_NODES) return;

    const int beg = row_ptr[n];
    const int end = row_ptr[n + 1];
    const float aldv = ald[n * H + h];

    // pass 1: max
    float mx = -INFINITY;
    for (int i = beg + lane; i < end; i += 32) {
        int s = csr_src[i];
        float v = als[s * H + h] + aldv;
        v = v > 0.f ? v : 0.2f * v;
        mx = fmaxf(mx, v);
    }
#pragma unroll
    for (int o = 16; o; o >>= 1) mx = fmaxf(mx, __shfl_xor_sync(0xffffffffu, mx, o));

    // pass 2: denom
    float den = 0.f;
    for (int i = beg + lane; i < end; i += 32) {
        int s = csr_src[i];
        float v = als[s * H + h] + aldv;
        v = v > 0.f ? v : 0.2f * v;
        den += __expf(v - mx);
    }
#pragma unroll
    for (int o = 16; o; o >>= 1) den += __shfl_xor_sync(0xffffffffu, den, o);
    const float inv = 1.0f / (den + 1e-16f);

    // pass 3: weighted gather, 2 edges in flight
    float4 acc = make_float4(0.f, 0.f, 0.f, 0.f);
    int i = beg;
    for (; i + 1 < end; i += 2) {
        int s0 = csr_src[i];
        int s1 = csr_src[i + 1];
        float v0 = als[s0 * H + h] + aldv;
        float v1 = als[s1 * H + h] + aldv;
        float4 f0 = ((const float4*)(feat + ((size_t)s0 * H + h) * CDIM))[lane];
        float4 f1 = ((const float4*)(feat + ((size_t)s1 * H + h) * CDIM))[lane];
        v0 = v0 > 0.f ? v0 : 0.2f * v0;
        v1 = v1 > 0.f ? v1 : 0.2f * v1;
        float a0 = __expf(v0 - mx) * inv;
        float a1 = __expf(v1 - mx) * inv;
        acc.x = fmaf(a0, f0.x, acc.x); acc.y = fmaf(a0, f0.y, acc.y);
        acc.z = fmaf(a0, f0.z, acc.z); acc.w = fmaf(a0, f0.w, acc.w);
        acc.x = fmaf(a1, f1.x, acc.x); acc.y = fmaf(a1, f1.y, acc.y);
        acc.z = fmaf(a1, f1.z, acc.z); acc.w = fmaf(a1, f1.w, acc.w);
    }
    if (i < end) {
        int s = csr_src[i];
        float v = als[s * H + h] + aldv;
        v = v > 0.f ? v : 0.2f * v;
        float a0 = __expf(v - mx) * inv;
        float4 f = ((const float4*)(feat + ((size_t)s * H + h) * CDIM))[lane];
        acc.x = fmaf(a0, f.x, acc.x); acc.y = fmaf(a0, f.y, acc.y);
        acc.z = fmaf(a0, f.z, acc.z); acc.w = fmaf(a0, f.w, acc.w);
    }
    float4 b4 = ((const float4*)(bias + h * CDIM))[lane];
    acc.x = fmaxf(acc.x + b4.x, 0.f);
    acc.y = fmaxf(acc.y + b4.y, 0.f);
    acc.z = fmaxf(acc.z + b4.z, 0.f);
    acc.w = fmaxf(acc.w + b4.w, 0.f);

    if (POOL) {
        float* p = pool + batch[n] * CDIM + lane * 4;
        atomicAdd(p + 0, acc.x);
        atomicAdd(p + 1, acc.y);
        atomicAdd(p + 2, acc.z);
        atomicAdd(p + 3, acc.w);
    } else {
        ((float4*)(out + ((size_t)n * H + h) * CDIM))[lane] = acc;
    }
}

// ---------------- classifier ---------------------------------------------------
__global__ void classifier(const float* __restrict__ pool, const float* __restrict__ cnt,
                           const float* __restrict__ Wc, const float* __restrict__ bc,
                           float* __restrict__ out) {
    int t = threadIdx.x;
    if (t >= NG * NOUT) return;
    int g = t / NOUT, o = t - g * NOUT;
    float inv = 1.0f / fmaxf(cnt[g], 1.0f);
    float sum = bc[o];
    for (int k = 0; k < CDIM; k++)
        sum = fmaf(pool[g * CDIM + k] * inv, Wc[k * NOUT + o], sum);
    out[t] = sum;
}

// ---------------- host orchestration ------------------------------------------
static inline int ceil_div(int a, int b) { return (a + b - 1) / b; }

extern "C" void kernel_launch(void* const* d_in, const int* in_sizes, int n_in,
                              void* d_out, int out_size) {
    const float* x      = (const float*)d_in[0];
    const int*   ei     = (const int*)d_in[1];
    const int*   batch  = (const int*)d_in[2];
    const float* W1     = (const float*)d_in[3];
    const float* asrc1  = (const float*)d_in[4];
    const float* adst1  = (const float*)d_in[5];
    const float* b1     = (const float*)d_in[6];
    const float* W2     = (const float*)d_in[7];
    const float* asrc2  = (const float*)d_in[8];
    const float* adst2  = (const float*)d_in[9];
    const float* b2     = (const float*)d_in[10];
    const float* Wc     = (const float*)d_in[11];
    const float* bc     = (const float*)d_in[12];
    float*       out    = (float*)d_out;

    float *zero, *h1, *out1, *als1, *ald1, *h2, *als2, *ald2;
    int *row_ptr, *cursor, *csr_src;
    cudaGetSymbolAddress((void**)&zero,    g_zero);
    cudaGetSymbolAddress((void**)&row_ptr, g_row_ptr);
    cudaGetSymbolAddress((void**)&cursor,  g_cursor);
    cudaGetSymbolAddress((void**)&csr_src, g_csr_src);
    cudaGetSymbolAddress((void**)&h1,   g_h1);
    cudaGetSymbolAddress((void**)&out1, g_out1);
    cudaGetSymbolAddress((void**)&als1, g_als1);
    cudaGetSymbolAddress((void**)&ald1, g_ald1);
    cudaGetSymbolAddress((void**)&h2,   g_h2);
    cudaGetSymbolAddress((void**)&als2, g_als2);
    cudaGetSymbolAddress((void**)&ald2, g_ald2);

    int*   deg  = (int*)(zero + Z_DEG);
    float* pool = zero + Z_POOL;
    float* cnt  = zero + Z_CNT;

    const int TB = 256;

    cudaFuncSetAttribute(gemm_tf32, cudaFuncAttributeMaxDynamicSharedMemorySize, GEMM_SMEM);

    // --- init + CSR build (+ pool counts piggybacked on hist) ---
    fill4_kernel<<<ceil_div(ZTOT / 4, TB), TB>>>((float4*)zero, 0.f, ZTOT / 4);
    hist_kernel<<<ceil_div(ETOT, TB), TB>>>(ei, deg, batch, cnt);
    scan_kernel<<<1, 1024>>>(deg, row_ptr, cursor);
    scatter_kernel<<<ceil_div(ETOT, TB), TB>>>(ei, cursor, csr_src);

    // --- layer 1 ---
    gemm_tf32<<<dim3(HC1 / 128, ceil_div(N_NODES, 128)), 256, GEMM_SMEM>>>(
        x, W1, h1, N_NODES, HC1, F_IN);
    att_logits<H1><<<ceil_div(N_NODES * H1, 8), 256>>>(h1, asrc1, adst1, als1, ald1);
    gat_fused<H1, false><<<ceil_div(N_NODES * H1 * 32, TB), TB>>>(
        row_ptr, csr_src, h1, als1, ald1, b1, out1, nullptr, nullptr);

    // --- layer 2 (output fused straight into pool) ---
    gemm_tf32<<<dim3(CDIM / 128, ceil_div(N_NODES, 128)), 256, GEMM_SMEM>>>(
        out1, W2, h2, N_NODES, CDIM, HC1);
    att_logits<1><<<ceil_div(N_NODES, 8), 256>>>(h2, asrc2, adst2, als2, ald2);
    gat_fused<1, true><<<ceil_div(N_NODES * 32, TB), TB>>>(
        row_ptr, csr_src, h2, als2, ald2, b2, nullptr, batch, pool);

    // --- classify ---
    classifier<<<1, NG * NOUT>>>(pool, cnt, Wc, bc, out);
}